// round 1
// baseline (speedup 1.0000x reference)
#include <cuda_runtime.h>

// Problem constants (BankedLinear: B=2, T=256, K=2, IN=OUT=512, NB=64)
#define NB        64
#define IN_DIM    512
#define OUT_DIM   512
#define KSEL      2
#define BT        512                 // B*T tokens
#define NENTRIES  (BT * KSEL)         // 1024 (token,k) entries

#define OUT_SPLIT 2
#define I_SPLIT   4
#define O_CHUNK   (OUT_DIM / OUT_SPLIT)   // 256 == blockDim.x (1 output/thread)
#define I_CHUNK   (IN_DIM / I_SPLIT)      // 128
#define TILE      16                      // token tile held in registers

__global__ void zero_out_kernel(float4* __restrict__ out, int n4) {
    int i = blockIdx.x * blockDim.x + threadIdx.x;
    if (i < n4) out[i] = make_float4(0.f, 0.f, 0.f, 0.f);
}

__global__ __launch_bounds__(O_CHUNK)
void banked_linear_kernel(const float* __restrict__ x,     // [BT, IN]
                          const int*   __restrict__ sel,   // [BT, K]
                          const float* __restrict__ prob,  // [BT, K]
                          const float* __restrict__ W,     // [NB, IN, OUT]
                          const float* __restrict__ bias,  // [NB, OUT]
                          float*       __restrict__ out)   // [BT, OUT]
{
    __shared__ int   s_tok[NENTRIES];
    __shared__ float s_prob[NENTRIES];
    __shared__ int   s_count;
    __shared__ float xs[TILE][I_CHUNK];

    const int bank  = blockIdx.x;
    const int oBase = blockIdx.y * O_CHUNK;
    const int iBase = blockIdx.z * I_CHUNK;
    const int tid   = threadIdx.x;

    if (tid == 0) s_count = 0;
    __syncthreads();

    // Build the (token, prob) list for this bank. 1024 entries / 256 thr = 4 each.
    for (int e = tid; e < NENTRIES; e += O_CHUNK) {
        if (sel[e] == bank) {
            int pos = atomicAdd(&s_count, 1);
            s_tok[pos]  = e / KSEL;
            s_prob[pos] = prob[e];
        }
    }
    __syncthreads();
    const int count = s_count;
    if (count == 0) return;

    // bias contribution is added exactly once (by the z==0 slice)
    const float bias_o = (blockIdx.z == 0) ? bias[bank * OUT_DIM + oBase + tid] : 0.0f;

    const float* Wb = W + (size_t)bank * IN_DIM * OUT_DIM
                        + (size_t)iBase * OUT_DIM + oBase + tid;

    for (int tt = 0; tt < count; tt += TILE) {
        const int nt = min(TILE, count - tt);

        // Stage the activation slice for this token tile (zero-pad unused rows
        // so the inner loop is branch-free).
        for (int j = tid; j < TILE * I_CHUNK; j += O_CHUNK) {
            int t = j / I_CHUNK;
            int i = j - t * I_CHUNK;
            xs[t][i] = (t < nt) ? x[(size_t)s_tok[tt + t] * IN_DIM + iBase + i] : 0.0f;
        }
        __syncthreads();

        float acc[TILE];
        #pragma unroll
        for (int t = 0; t < TILE; t++) acc[t] = 0.0f;

        // Stream the weight slice: one coalesced row-load per i, 16 FMAs/thread.
        #pragma unroll 4
        for (int i = 0; i < I_CHUNK; i++) {
            const float w = Wb[(size_t)i * OUT_DIM];
            #pragma unroll
            for (int t = 0; t < TILE; t++)
                acc[t] = fmaf(xs[t][i], w, acc[t]);
        }

        // Scatter: prob-weighted partial sums (atomics combine I-splits and
        // the K=2 contributions per token).
        for (int t = 0; t < nt; t++) {
            const float p = s_prob[tt + t];
            const float v = p * (acc[t] + bias_o);
            atomicAdd(&out[(size_t)s_tok[tt + t] * OUT_DIM + oBase + tid], v);
        }
        __syncthreads();
    }
}

extern "C" void kernel_launch(void* const* d_in, const int* in_sizes, int n_in,
                              void* d_out, int out_size) {
    const float* x    = (const float*)d_in[0];
    const int*   sel  = (const int*)  d_in[1];
    const float* prob = (const float*)d_in[2];
    const float* W    = (const float*)d_in[3];
    const float* bias = (const float*)d_in[4];
    float* out = (float*)d_out;

    // d_out is poisoned; zero it before atomic accumulation.
    int n4 = out_size / 4;
    zero_out_kernel<<<(n4 + 255) / 256, 256>>>((float4*)out, n4);

    dim3 grid(NB, OUT_SPLIT, I_SPLIT);
    banked_linear_kernel<<<grid, O_CHUNK>>>(x, sel, prob, W, bias, out);
}

// round 3
// speedup vs baseline: 1.1412x; 1.1412x over previous
#include <cuda_runtime.h>

// BankedLinear: B=2, T=256, K=2, IN=OUT=512, NB=64
#define NB       64
#define IN_DIM   512
#define OUT_DIM  512
#define KSEL     2
#define BT       512
#define NENT     (BT * KSEL)      // 1024 (token,k) entries
#define O_SPLIT  8
#define O_CHUNK  (OUT_DIM / O_SPLIT)   // 64 outputs per CTA
#define TTILE    16                    // tokens per tile
#define NTHREADS 128                   // 32 out-groups (2 outs) x 4 token-groups (4 tokens)

__global__ void zero_out_kernel(float4* __restrict__ out, int n4) {
    int i = blockIdx.x * blockDim.x + threadIdx.x;
    if (i < n4) out[i] = make_float4(0.f, 0.f, 0.f, 0.f);
}

__global__ __launch_bounds__(NTHREADS)
void banked_linear_kernel(const float* __restrict__ x,     // [BT, IN]
                          const int*   __restrict__ sel,   // [BT, K]
                          const float* __restrict__ prob,  // [BT, K]
                          const float* __restrict__ W,     // [NB, IN, OUT]
                          const float* __restrict__ bias,  // [NB, OUT]
                          float*       __restrict__ out)   // [BT, OUT]
{
    // xs FIRST and 16B-aligned: it is read with LDS.128.
    __shared__ __align__(16) float xs[IN_DIM * TTILE];  // transposed xs[i*16+t], prob-prescaled, 32 KB
    __shared__ int   s_tok[NENT];      // 4 KB
    __shared__ float s_prob[NENT];     // 4 KB
    __shared__ int   s_count;

    const int bank  = blockIdx.x;
    const int oBase = blockIdx.y * O_CHUNK;
    const int tid   = threadIdx.x;
    const int tg    = tid & 3;    // token group: tokens tg*4 .. tg*4+3
    const int og    = tid >> 2;   // out group:   outs og*2, og*2+1

    if (tid == 0) s_count = 0;
    __syncthreads();

    // Build (token, prob) list for this bank.
    for (int e = tid; e < NENT; e += NTHREADS) {
        if (sel[e] == bank) {
            int pos = atomicAdd(&s_count, 1);
            s_tok[pos]  = e / KSEL;
            s_prob[pos] = prob[e];
        }
    }
    __syncthreads();
    const int count = s_count;
    if (count == 0) return;

    // This CTA's W slice: rows i, columns [oBase, oBase+64). Thread reads 2 outs.
    const float2* Wp = (const float2*)(W + (size_t)bank * IN_DIM * OUT_DIM + oBase) + og;
    const float2  b2 = *((const float2*)(bias + (size_t)bank * OUT_DIM + oBase) + og);

    for (int tt = 0; tt < count; tt += TTILE) {
        // ── Stage x tile, transposed + pre-scaled by prob, zero-padded ──
        for (int j = tid; j < (IN_DIM / 4) * TTILE; j += NTHREADS) {
            int ii4 = j >> 4;          // which float4 along IN
            int t   = j & 15;          // token slot
            int e   = tt + t;
            float4 v = make_float4(0.f, 0.f, 0.f, 0.f);
            float  p = 0.f;
            if (e < count) {
                p = s_prob[e];
                v = *(const float4*)(x + (size_t)s_tok[e] * IN_DIM + ii4 * 4);
            }
            xs[(ii4 * 4 + 0) * TTILE + t] = v.x * p;
            xs[(ii4 * 4 + 1) * TTILE + t] = v.y * p;
            xs[(ii4 * 4 + 2) * TTILE + t] = v.z * p;
            xs[(ii4 * 4 + 3) * TTILE + t] = v.w * p;
        }
        __syncthreads();

        // ── Register-tiled outer product: 4 tokens x 2 outs per thread ──
        float acc[4][2];
        #pragma unroll
        for (int t = 0; t < 4; t++) { acc[t][0] = 0.f; acc[t][1] = 0.f; }

        #pragma unroll 1
        for (int i = 0; i < IN_DIM; i += 4) {
            float4 xf[4];
            float2 wf[4];
            #pragma unroll
            for (int u = 0; u < 4; u++) {
                xf[u] = *(const float4*)&xs[(i + u) * TTILE + tg * 4];
                wf[u] = Wp[(size_t)(i + u) * (OUT_DIM / 2)];
            }
            #pragma unroll
            for (int u = 0; u < 4; u++) {
                acc[0][0] = fmaf(xf[u].x, wf[u].x, acc[0][0]);
                acc[0][1] = fmaf(xf[u].x, wf[u].y, acc[0][1]);
                acc[1][0] = fmaf(xf[u].y, wf[u].x, acc[1][0]);
                acc[1][1] = fmaf(xf[u].y, wf[u].y, acc[1][1]);
                acc[2][0] = fmaf(xf[u].z, wf[u].x, acc[2][0]);
                acc[2][1] = fmaf(xf[u].z, wf[u].y, acc[2][1]);
                acc[3][0] = fmaf(xf[u].w, wf[u].x, acc[3][0]);
                acc[3][1] = fmaf(xf[u].w, wf[u].y, acc[3][1]);
            }
        }

        // ── Epilogue: acc already prob-weighted; add p*bias; combine via atomics ──
        #pragma unroll
        for (int t = 0; t < 4; t++) {
            int e = tt + tg * 4 + t;
            if (e < count) {
                int   tok = s_tok[e];
                float p   = s_prob[e];
                float* po = out + (size_t)tok * OUT_DIM + oBase + og * 2;
                atomicAdd(po + 0, acc[t][0] + p * b2.x);
                atomicAdd(po + 1, acc[t][1] + p * b2.y);
            }
        }
        __syncthreads();
    }
}

extern "C" void kernel_launch(void* const* d_in, const int* in_sizes, int n_in,
                              void* d_out, int out_size) {
    const float* x    = (const float*)d_in[0];
    const int*   sel  = (const int*)  d_in[1];
    const float* prob = (const float*)d_in[2];
    const float* W    = (const float*)d_in[3];
    const float* bias = (const float*)d_in[4];
    float* out = (float*)d_out;

    int n4 = out_size / 4;
    zero_out_kernel<<<(n4 + 255) / 256, 256>>>((float4*)out, n4);

    dim3 grid(NB, O_SPLIT);
    banked_linear_kernel<<<grid, NTHREADS>>>(x, sel, prob, W, bias, out);
}

// round 4
// speedup vs baseline: 1.4484x; 1.2693x over previous
#include <cuda_runtime.h>

// BankedLinear: B=2, T=256, K=2, IN=OUT=512, NB=64
#define NB       64
#define IN_DIM   512
#define OUT_DIM  512
#define KSEL     2
#define BT       512
#define NENT     (BT * KSEL)            // 1024 (token,k) entries
#define O_SPLIT  4
#define O_CHUNK  (OUT_DIM / O_SPLIT)    // 128 outs per CTA
#define I_SPLIT  2
#define I_CHUNK  (IN_DIM / I_SPLIT)     // 256
#define CHUNK_I  16                     // i-rows per cp.async stage
#define NCHUNK   (I_CHUNK / CHUNK_I)    // 16
#define TTILE    16                     // tokens per tile
#define NTHREADS 256                    // 64 out-groups(2 outs) x 4 token-groups(4 tokens)

__device__ __forceinline__ void cp_async16(void* dst, const void* src) {
    unsigned d = (unsigned)__cvta_generic_to_shared(dst);
    asm volatile("cp.async.cg.shared.global [%0], [%1], 16;\n" :: "r"(d), "l"(src));
}
#define CP_COMMIT() asm volatile("cp.async.commit_group;\n" ::)
#define CP_WAIT1()  asm volatile("cp.async.wait_group 1;\n" ::)
#define CP_WAIT0()  asm volatile("cp.async.wait_group 0;\n" ::)

__global__ void zero_out_kernel(float4* __restrict__ out, int n4) {
    int i = blockIdx.x * blockDim.x + threadIdx.x;
    if (i < n4) out[i] = make_float4(0.f, 0.f, 0.f, 0.f);
}

__global__ __launch_bounds__(NTHREADS)
void banked_linear_kernel(const float* __restrict__ x,     // [BT, IN]
                          const int*   __restrict__ sel,   // [BT, K]
                          const float* __restrict__ prob,  // [BT, K]
                          const float* __restrict__ W,     // [NB, IN, OUT]
                          const float* __restrict__ bias,  // [NB, OUT]
                          float*       __restrict__ out)   // [BT, OUT]
{
    __shared__ __align__(16) float xs[I_CHUNK * TTILE];          // 16 KB, xs[i*16+t], prob-prescaled
    __shared__ __align__(16) float ws[2][CHUNK_I][O_CHUNK];      // 2 x 8 KB W pipeline
    __shared__ int   s_tok[NENT];                                // 4 KB
    __shared__ float s_prob[NENT];                               // 4 KB
    __shared__ int   s_count;

    const int bank  = blockIdx.x;
    const int oBase = blockIdx.y * O_CHUNK;
    const int iBase = blockIdx.z * I_CHUNK;
    const int tid   = threadIdx.x;
    const int tg    = tid & 3;     // 4 tokens: tg*4 .. tg*4+3
    const int og    = tid >> 2;    // 2 outs:   og*2, og*2+1

    if (tid == 0) s_count = 0;
    __syncthreads();

    for (int e = tid; e < NENT; e += NTHREADS) {
        if (sel[e] == bank) {
            int pos = atomicAdd(&s_count, 1);
            s_tok[pos]  = e / KSEL;
            s_prob[pos] = prob[e];
        }
    }
    __syncthreads();
    const int count = s_count;
    if (count == 0) return;

    const float* Wc = W + (size_t)bank * IN_DIM * OUT_DIM + (size_t)iBase * OUT_DIM + oBase;
    const float2 b2 = (blockIdx.z == 0)
                    ? *((const float2*)(bias + (size_t)bank * OUT_DIM + oBase) + og)
                    : make_float2(0.f, 0.f);

    for (int tt = 0; tt < count; tt += TTILE) {
        // ── prologue: kick off W chunk 0 (overlaps with xs staging below) ──
        #pragma unroll
        for (int k = 0; k < 2; k++) {
            int j = tid + k * NTHREADS;          // 512 float4s = 8 KB chunk
            int row = j >> 5, c4 = j & 31;
            cp_async16(&ws[0][row][c4 * 4], Wc + (size_t)row * OUT_DIM + c4 * 4);
        }
        CP_COMMIT();

        // ── stage x tile: transposed + prob-prescaled + zero-padded ──
        #pragma unroll
        for (int k = 0; k < 4; k++) {
            int j   = tid + k * NTHREADS;        // (I_CHUNK/4)*TTILE = 1024
            int ii4 = j >> 4;
            int t   = j & 15;
            int e   = tt + t;
            float4 v = make_float4(0.f, 0.f, 0.f, 0.f);
            float  p = 0.f;
            if (e < count) {
                p = s_prob[e];
                v = *(const float4*)(x + (size_t)s_tok[e] * IN_DIM + iBase + ii4 * 4);
            }
            xs[(ii4 * 4 + 0) * TTILE + t] = v.x * p;
            xs[(ii4 * 4 + 1) * TTILE + t] = v.y * p;
            xs[(ii4 * 4 + 2) * TTILE + t] = v.z * p;
            xs[(ii4 * 4 + 3) * TTILE + t] = v.w * p;
        }
        __syncthreads();

        float acc[4][2];
        #pragma unroll
        for (int t = 0; t < 4; t++) { acc[t][0] = 0.f; acc[t][1] = 0.f; }

        // ── chunked mainloop: cp.async double buffer over 16 W chunks ──
        for (int c = 0; c < NCHUNK; c++) {
            const int st = c & 1;
            if (c + 1 < NCHUNK) {
                #pragma unroll
                for (int k = 0; k < 2; k++) {
                    int j = tid + k * NTHREADS;
                    int row = j >> 5, c4 = j & 31;
                    cp_async16(&ws[st ^ 1][row][c4 * 4],
                               Wc + (size_t)((c + 1) * CHUNK_I + row) * OUT_DIM + c4 * 4);
                }
                CP_COMMIT();
                CP_WAIT1();     // chunk c complete (c+1 may be in flight)
            } else {
                CP_WAIT0();
            }
            __syncthreads();    // make chunk c visible to all threads

            #pragma unroll
            for (int u4 = 0; u4 < CHUNK_I / 4; u4++) {
                float4 xf[4];
                float2 wf[4];
                #pragma unroll
                for (int u = 0; u < 4; u++) {
                    int il = c * CHUNK_I + u4 * 4 + u;
                    xf[u] = *(const float4*)&xs[il * TTILE + tg * 4];
                    wf[u] = *(const float2*)&ws[st][u4 * 4 + u][og * 2];
                }
                #pragma unroll
                for (int u = 0; u < 4; u++) {
                    acc[0][0] = fmaf(xf[u].x, wf[u].x, acc[0][0]);
                    acc[0][1] = fmaf(xf[u].x, wf[u].y, acc[0][1]);
                    acc[1][0] = fmaf(xf[u].y, wf[u].x, acc[1][0]);
                    acc[1][1] = fmaf(xf[u].y, wf[u].y, acc[1][1]);
                    acc[2][0] = fmaf(xf[u].z, wf[u].x, acc[2][0]);
                    acc[2][1] = fmaf(xf[u].z, wf[u].y, acc[2][1]);
                    acc[3][0] = fmaf(xf[u].w, wf[u].x, acc[3][0]);
                    acc[3][1] = fmaf(xf[u].w, wf[u].y, acc[3][1]);
                }
            }
            __syncthreads();    // protect stage st^1 / xs from next-iter overwrite
        }

        // ── epilogue: acc is prob-weighted; add p*bias once (z==0); combine via atomics ──
        #pragma unroll
        for (int t = 0; t < 4; t++) {
            int e = tt + tg * 4 + t;
            if (e < count) {
                int   tok = s_tok[e];
                float p   = s_prob[e];
                float* po = out + (size_t)tok * OUT_DIM + oBase + og * 2;
                atomicAdd(po + 0, acc[t][0] + p * b2.x);
                atomicAdd(po + 1, acc[t][1] + p * b2.y);
            }
        }
        __syncthreads();
    }
}

extern "C" void kernel_launch(void* const* d_in, const int* in_sizes, int n_in,
                              void* d_out, int out_size) {
    const float* x    = (const float*)d_in[0];
    const int*   sel  = (const int*)  d_in[1];
    const float* prob = (const float*)d_in[2];
    const float* W    = (const float*)d_in[3];
    const float* bias = (const float*)d_in[4];
    float* out = (float*)d_out;

    int n4 = out_size / 4;
    zero_out_kernel<<<(n4 + 255) / 256, 256>>>((float4*)out, n4);

    dim3 grid(NB, O_SPLIT, I_SPLIT);
    banked_linear_kernel<<<grid, NTHREADS>>>(x, sel, prob, W, bias, out);
}

// round 6
// speedup vs baseline: 1.7370x; 1.1993x over previous
#include <cuda_runtime.h>
#include <cstdint>

// BankedLinear: B=2, T=256, K=2, IN=OUT=512, NB=64
#define NB       64
#define IN_DIM   512
#define OUT_DIM  512
#define KSEL     2
#define NENT     1024                 // (token,k) entries
#define O_SPLIT  4
#define O_CHUNK  (OUT_DIM / O_SPLIT)  // 128 outs per CTA
#define MTOK     16                   // token tile (MMA M)
#define NTHR     256                  // 8 warps; warp owns 16 outs (2 n-tiles of 8)
#define NKSTEP   (IN_DIM / 8)         // 64 k8-steps

__global__ void zero_out_kernel(float4* __restrict__ out, int n4) {
    int i = blockIdx.x * blockDim.x + threadIdx.x;
    if (i < n4) out[i] = make_float4(0.f, 0.f, 0.f, 0.f);
}

__device__ __forceinline__ uint32_t f2tf(float f) {
    uint32_t r;
    asm("cvt.rna.tf32.f32 %0, %1;" : "=r"(r) : "f"(f));
    return r;
}
__device__ __forceinline__ void split_tf32(float f, uint32_t& h, uint32_t& l) {
    h = f2tf(f);
    l = f2tf(f - __uint_as_float(h));
}
__device__ __forceinline__ void mma8(float* c, const uint32_t* a, const uint32_t* b) {
    asm volatile(
        "mma.sync.aligned.m16n8k8.row.col.f32.tf32.tf32.f32 "
        "{%0,%1,%2,%3}, {%4,%5,%6,%7}, {%8,%9}, {%0,%1,%2,%3};"
        : "+f"(c[0]), "+f"(c[1]), "+f"(c[2]), "+f"(c[3])
        : "r"(a[0]), "r"(a[1]), "r"(a[2]), "r"(a[3]), "r"(b[0]), "r"(b[1]));
}

__global__ __launch_bounds__(NTHR)
void banked_linear_mma(const float* __restrict__ x,     // [BT, IN]
                       const int*   __restrict__ sel,   // [BT, K]
                       const float* __restrict__ prob,  // [BT, K]
                       const float* __restrict__ W,     // [NB, IN, OUT]
                       const float* __restrict__ bias,  // [NB, OUT]
                       float*       __restrict__ out)   // [BT, OUT]
{
    __shared__ float xs[IN_DIM * MTOK];   // [k][t], prob-prescaled fp32, 32 KB
    __shared__ int   s_tok[NENT];         // 4 KB
    __shared__ float s_prob[NENT];        // 4 KB
    __shared__ int   s_cnt;

    const int bank  = blockIdx.x;
    const int oBase = blockIdx.y * O_CHUNK;
    const int tid   = threadIdx.x;
    const int warp  = tid >> 5;
    const int lane  = tid & 31;
    const int gr    = lane >> 2;   // group id 0..7
    const int tg    = lane & 3;    // thread-in-group 0..3
    const int o0    = oBase + warp * 16;

    if (tid == 0) s_cnt = 0;
    __syncthreads();

    // Build (token, prob) list for this bank.
    for (int e = tid; e < NENT; e += NTHR) {
        if (sel[e] == bank) {
            int pos = atomicAdd(&s_cnt, 1);
            s_tok[pos]  = e / KSEL;
            s_prob[pos] = prob[e];
        }
    }
    __syncthreads();
    const int count = s_cnt;
    if (count == 0) return;

    // B-fragment gmem base: element (k-row = kb+tg(+4), n-col = o0 + nt*8 + gr)
    const float* Wt = W + (size_t)bank * IN_DIM * OUT_DIM + (size_t)tg * OUT_DIM + o0 + gr;

    for (int tt = 0; tt < count; tt += MTOK) {
        // ── Stage x tile: transposed [k][t], prob-prescaled, zero-padded ──
        #pragma unroll
        for (int r = 0; r < 8; r++) {
            int j  = tid + r * NTHR;        // 2048 = 128 k4-groups x 16 tokens
            int t  = j & 15;
            int k4 = j >> 4;
            int e  = tt + t;
            float4 v = make_float4(0.f, 0.f, 0.f, 0.f);
            float  p = 0.f;
            if (e < count) {
                p = s_prob[e];
                v = *(const float4*)(x + (size_t)s_tok[e] * IN_DIM + k4 * 4);
            }
            xs[(k4 * 4 + 0) * MTOK + t] = v.x * p;
            xs[(k4 * 4 + 1) * MTOK + t] = v.y * p;
            xs[(k4 * 4 + 2) * MTOK + t] = v.z * p;
            xs[(k4 * 4 + 3) * MTOK + t] = v.w * p;
        }
        __syncthreads();

        float c0[4] = {0.f, 0.f, 0.f, 0.f};
        float c1[4] = {0.f, 0.f, 0.f, 0.f};

        // ── Mainloop: 64 k8-steps, 3-term tf32 split, 6 HMMA per step ──
        #pragma unroll 4
        for (int ks = 0; ks < NKSTEP; ks++) {
            const int kb = ks * 8;

            // A fragment (x): rows = tokens gr, gr+8; cols = kb+tg, kb+tg+4
            const float* xp = xs + (kb + tg) * MTOK;
            float xa0 = xp[gr];
            float xa1 = xp[gr + 8];
            float xa2 = xp[4 * MTOK + gr];
            float xa3 = xp[4 * MTOK + gr + 8];

            // B fragments (W): rows kb+tg, kb+tg+4; cols o0 + nt*8 + gr
            const float* wp = Wt + (size_t)kb * OUT_DIM;
            float w00 = wp[0];
            float w01 = wp[4 * OUT_DIM];
            float w10 = wp[8];
            float w11 = wp[4 * OUT_DIM + 8];

            uint32_t ah[4], al[4];
            split_tf32(xa0, ah[0], al[0]);
            split_tf32(xa1, ah[1], al[1]);
            split_tf32(xa2, ah[2], al[2]);
            split_tf32(xa3, ah[3], al[3]);

            uint32_t bh0[2], bl0[2], bh1[2], bl1[2];
            split_tf32(w00, bh0[0], bl0[0]);
            split_tf32(w01, bh0[1], bl0[1]);
            split_tf32(w10, bh1[0], bl1[0]);
            split_tf32(w11, bh1[1], bl1[1]);

            mma8(c0, ah, bh0);
            mma8(c0, al, bh0);
            mma8(c0, ah, bl0);
            mma8(c1, ah, bh1);
            mma8(c1, al, bh1);
            mma8(c1, ah, bl1);
        }

        // ── Epilogue: C-fragment scatter, prob-weighted bias, atomic combine ──
        #pragma unroll
        for (int nt = 0; nt < 2; nt++) {
            const float* cc  = nt ? c1 : c0;
            const int   colb = o0 + nt * 8 + tg * 2;
            const float2 bb  = *(const float2*)(bias + (size_t)bank * OUT_DIM + colb);

            int e0 = tt + gr;
            if (e0 < count) {
                float p = s_prob[e0];
                float* po = out + (size_t)s_tok[e0] * OUT_DIM + colb;
                atomicAdd(po + 0, cc[0] + p * bb.x);
                atomicAdd(po + 1, cc[1] + p * bb.y);
            }
            int e1 = tt + gr + 8;
            if (e1 < count) {
                float p = s_prob[e1];
                float* po = out + (size_t)s_tok[e1] * OUT_DIM + colb;
                atomicAdd(po + 0, cc[2] + p * bb.x);
                atomicAdd(po + 1, cc[3] + p * bb.y);
            }
        }
        __syncthreads();   // xs reuse barrier for next token tile
    }
}

extern "C" void kernel_launch(void* const* d_in, const int* in_sizes, int n_in,
                              void* d_out, int out_size) {
    const float* x    = (const float*)d_in[0];
    const int*   sel  = (const int*)  d_in[1];
    const float* prob = (const float*)d_in[2];
    const float* W    = (const float*)d_in[3];
    const float* bias = (const float*)d_in[4];
    float* out = (float*)d_out;

    int n4 = out_size / 4;
    zero_out_kernel<<<(n4 + 255) / 256, 256>>>((float4*)out, n4);

    dim3 grid(NB, O_SPLIT);
    banked_linear_mma<<<grid, NTHR>>>(x, sel, prob, W, bias, out);
}

// round 7
// speedup vs baseline: 1.9475x; 1.1211x over previous
#include <cuda_runtime.h>
#include <cstdint>

// BankedLinear: B=2, T=256, K=2, IN=OUT=512, NB=64
#define NB       64
#define IN_DIM   512
#define OUT_DIM  512
#define KSEL     2
#define NENT     1024                 // (token,k) entries
#define O_SPLIT  4
#define O_CHUNK  (OUT_DIM / O_SPLIT)  // 128 outs per CTA
#define K_SPLIT  2
#define KRANGE   (IN_DIM / K_SPLIT)   // 256 k-rows per CTA
#define NKS      (KRANGE / 8)         // 32 local k8-steps
#define NGRP     (NKS / 8)            // 4 groups of 8 ksteps
#define MTOK     16                   // token tile (MMA M)
#define NTHR     256                  // 8 warps; warp owns 16 outs

__global__ void zero_out_kernel(float4* __restrict__ out, int n4) {
    int i = blockIdx.x * blockDim.x + threadIdx.x;
    if (i < n4) out[i] = make_float4(0.f, 0.f, 0.f, 0.f);
}

__device__ __forceinline__ uint32_t f2tf(float f) {
    uint32_t r;
    asm("cvt.rna.tf32.f32 %0, %1;" : "=r"(r) : "f"(f));
    return r;
}
__device__ __forceinline__ void split_tf32(float f, uint32_t& h, uint32_t& l) {
    h = f2tf(f);
    l = f2tf(f - __uint_as_float(h));
}
__device__ __forceinline__ void mma8(float* c, const uint32_t* a, const uint32_t* b) {
    asm volatile(
        "mma.sync.aligned.m16n8k8.row.col.f32.tf32.tf32.f32 "
        "{%0,%1,%2,%3}, {%4,%5,%6,%7}, {%8,%9}, {%0,%1,%2,%3};"
        : "+f"(c[0]), "+f"(c[1]), "+f"(c[2]), "+f"(c[3])
        : "r"(a[0]), "r"(a[1]), "r"(a[2]), "r"(a[3]), "r"(b[0]), "r"(b[1]));
}

__global__ __launch_bounds__(NTHR)
void banked_linear_mma(const float* __restrict__ x,     // [BT, IN]
                       const int*   __restrict__ sel,   // [BT, K]
                       const float* __restrict__ prob,  // [BT, K]
                       const float* __restrict__ W,     // [NB, IN, OUT]
                       const float* __restrict__ bias,  // [NB, OUT]
                       float*       __restrict__ out)   // [BT, OUT]
{
    // xs in A-fragment order: xs[ks*128 + lane*4 + reg] -> one LDS.128 per kstep
    __shared__ __align__(16) float xs[NKS * 128];   // 16 KB
    __shared__ int   s_tok[NENT];                   // 4 KB
    __shared__ float s_prob[NENT];                  // 4 KB
    __shared__ int   s_cnt;

    const int bank  = blockIdx.x;
    const int oBase = blockIdx.y * O_CHUNK;
    const int kOff  = blockIdx.z * KRANGE;
    const int tid   = threadIdx.x;
    const int warp  = tid >> 5;
    const int lane  = tid & 31;
    const int gr    = lane >> 2;   // group id 0..7
    const int tg    = lane & 3;    // thread-in-group 0..3
    const int o0    = oBase + warp * 16;

    if (tid == 0) s_cnt = 0;
    __syncthreads();

    for (int e = tid; e < NENT; e += NTHR) {
        if (sel[e] == bank) {
            int pos = atomicAdd(&s_cnt, 1);
            s_tok[pos]  = e / KSEL;
            s_prob[pos] = prob[e];
        }
    }
    __syncthreads();
    const int count = s_cnt;
    if (count == 0) return;

    // B-fragment gmem base: W[kOff + kb + tg (+4)][o0 + nt*8 + gr]
    const float* Wt = W + (size_t)bank * IN_DIM * OUT_DIM
                        + (size_t)(kOff + tg) * OUT_DIM + o0 + gr;

    for (int tt = 0; tt < count; tt += MTOK) {
        // ── Stage x tile directly in A-fragment layout (prescaled, padded) ──
        #pragma unroll
        for (int r = 0; r < 4; r++) {
            int j  = tid + r * NTHR;        // 1024 = 64 k4-groups x 16 tokens
            int t  = j & 15;
            int k4 = j >> 4;
            int e  = tt + t;
            float4 v = make_float4(0.f, 0.f, 0.f, 0.f);
            float  p = 0.f;
            if (e < count) {
                p = s_prob[e];
                v = *(const float4*)(x + (size_t)s_tok[e] * IN_DIM + kOff + k4 * 4);
            }
            // element (k = k4*4+i, t): lane = (t&7)*4 + i, reg = (k4&1)*2 + (t>>3)
            int ks = k4 >> 1;
            int rg = (k4 & 1) * 2 + (t >> 3);
            int lb = (t & 7) * 4;
            float* xp = &xs[ks * 128 + rg];
            xp[(lb + 0) * 4] = v.x * p;
            xp[(lb + 1) * 4] = v.y * p;
            xp[(lb + 2) * 4] = v.z * p;
            xp[(lb + 3) * 4] = v.w * p;
        }

        // ── Prefetch W group 0 (overlaps staging barrier) ──
        float w[2][8][4];
        #pragma unroll
        for (int g = 0; g < 8; g++) {
            const float* wp = Wt + (size_t)(g * 8) * OUT_DIM;
            w[0][g][0] = wp[0];
            w[0][g][1] = wp[4 * OUT_DIM];
            w[0][g][2] = wp[8];
            w[0][g][3] = wp[4 * OUT_DIM + 8];
        }
        __syncthreads();

        float c0[4] = {0.f, 0.f, 0.f, 0.f};
        float c1[4] = {0.f, 0.f, 0.f, 0.f};

        // ── Mainloop: 4 groups x 8 ksteps; next group's W issued before compute ──
        #pragma unroll
        for (int grp = 0; grp < NGRP; grp++) {
            const int cur = grp & 1;
            if (grp + 1 < NGRP) {
                #pragma unroll
                for (int g = 0; g < 8; g++) {
                    const float* wp = Wt + (size_t)((grp + 1) * 64 + g * 8) * OUT_DIM;
                    w[cur ^ 1][g][0] = wp[0];
                    w[cur ^ 1][g][1] = wp[4 * OUT_DIM];
                    w[cur ^ 1][g][2] = wp[8];
                    w[cur ^ 1][g][3] = wp[4 * OUT_DIM + 8];
                }
            }
            #pragma unroll
            for (int g = 0; g < 8; g++) {
                const int ks = grp * 8 + g;
                float4 xa = *(const float4*)&xs[ks * 128 + lane * 4];

                uint32_t ah[4], al[4];
                split_tf32(xa.x, ah[0], al[0]);
                split_tf32(xa.y, ah[1], al[1]);
                split_tf32(xa.z, ah[2], al[2]);
                split_tf32(xa.w, ah[3], al[3]);

                uint32_t bh0[2], bl0[2], bh1[2], bl1[2];
                split_tf32(w[cur][g][0], bh0[0], bl0[0]);
                split_tf32(w[cur][g][1], bh0[1], bl0[1]);
                split_tf32(w[cur][g][2], bh1[0], bl1[0]);
                split_tf32(w[cur][g][3], bh1[1], bl1[1]);

                mma8(c0, ah, bh0);
                mma8(c0, al, bh0);
                mma8(c0, ah, bl0);
                mma8(c1, ah, bh1);
                mma8(c1, al, bh1);
                mma8(c1, ah, bl1);
            }
        }

        // ── Epilogue: C-fragment scatter; bias only from the z==0 K-half ──
        #pragma unroll
        for (int nt = 0; nt < 2; nt++) {
            const float* cc  = nt ? c1 : c0;
            const int   colb = o0 + nt * 8 + tg * 2;
            float2 bb = make_float2(0.f, 0.f);
            if (kOff == 0) bb = *(const float2*)(bias + (size_t)bank * OUT_DIM + colb);

            int e0 = tt + gr;
            if (e0 < count) {
                float p = s_prob[e0];
                float* po = out + (size_t)s_tok[e0] * OUT_DIM + colb;
                atomicAdd(po + 0, cc[0] + p * bb.x);
                atomicAdd(po + 1, cc[1] + p * bb.y);
            }
            int e1 = tt + gr + 8;
            if (e1 < count) {
                float p = s_prob[e1];
                float* po = out + (size_t)s_tok[e1] * OUT_DIM + colb;
                atomicAdd(po + 0, cc[2] + p * bb.x);
                atomicAdd(po + 1, cc[3] + p * bb.y);
            }
        }
        __syncthreads();   // xs reuse barrier for next token tile
    }
}

extern "C" void kernel_launch(void* const* d_in, const int* in_sizes, int n_in,
                              void* d_out, int out_size) {
    const float* x    = (const float*)d_in[0];
    const int*   sel  = (const int*)  d_in[1];
    const float* prob = (const float*)d_in[2];
    const float* W    = (const float*)d_in[3];
    const float* bias = (const float*)d_in[4];
    float* out = (float*)d_out;

    int n4 = out_size / 4;
    zero_out_kernel<<<(n4 + 255) / 256, 256>>>((float4*)out, n4);

    dim3 grid(NB, O_SPLIT, K_SPLIT);
    banked_linear_mma<<<grid, NTHR>>>(x, sel, prob, W, bias, out);
}

// round 9
// speedup vs baseline: 2.1575x; 1.1078x over previous
#include <cuda_runtime.h>
#include <cstdint>

// BankedLinear: B=2, T=256, K=2, IN=OUT=512, NB=64
#define NB       64
#define IN_DIM   512
#define OUT_DIM  512
#define KSEL     2
#define NENT     1024                 // (token,k) entries
#define O_SPLIT  4
#define O_CHUNK  (OUT_DIM / O_SPLIT)  // 128 outs per CTA
#define K_SPLIT  2
#define KRANGE   (IN_DIM / K_SPLIT)   // 256 k-rows per CTA
#define NKS      (KRANGE / 8)         // 32 local k8-steps
#define GSTEP    4                    // ksteps per W prefetch group
#define NGRP     (NKS / GSTEP)        // 8
#define MTOK     16                   // token tile (MMA M)
#define NTHR     256                  // 8 warps; warp owns 16 outs

__global__ void zero_out_kernel(float4* __restrict__ out, int n4) {
    int i = blockIdx.x * blockDim.x + threadIdx.x;
    if (i < n4) out[i] = make_float4(0.f, 0.f, 0.f, 0.f);
}

__device__ __forceinline__ uint32_t f2tf(float f) {
    uint32_t r;
    asm("cvt.rna.tf32.f32 %0, %1;" : "=r"(r) : "f"(f));
    return r;
}
__device__ __forceinline__ void split_tf32(float f, uint32_t& h, uint32_t& l) {
    h = f2tf(f);
    l = f2tf(f - __uint_as_float(h));
}
__device__ __forceinline__ void mma8(float* c, const uint32_t* a, const uint32_t* b) {
    asm volatile(
        "mma.sync.aligned.m16n8k8.row.col.f32.tf32.tf32.f32 "
        "{%0,%1,%2,%3}, {%4,%5,%6,%7}, {%8,%9}, {%0,%1,%2,%3};"
        : "+f"(c[0]), "+f"(c[1]), "+f"(c[2]), "+f"(c[3])
        : "r"(a[0]), "r"(a[1]), "r"(a[2]), "r"(a[3]), "r"(b[0]), "r"(b[1]));
}

__global__ __launch_bounds__(NTHR, 2)
void banked_linear_mma(const float* __restrict__ x,     // [BT, IN]
                       const int*   __restrict__ sel,   // [BT, K]
                       const float* __restrict__ prob,  // [BT, K]
                       const float* __restrict__ W,     // [NB, IN, OUT]
                       const float* __restrict__ bias,  // [NB, OUT]
                       float*       __restrict__ out)   // [BT, OUT]
{
    // x pre-split to tf32 hi/lo, stored in A-fragment order:
    //   xs_{h,l}[ks*128 + lane*4 + reg]  -> one LDS.128 each per kstep
    __shared__ __align__(16) uint32_t xs_h[NKS * 128];   // 16 KB
    __shared__ __align__(16) uint32_t xs_l[NKS * 128];   // 16 KB
    __shared__ int   s_tok[NENT];                        // 4 KB
    __shared__ float s_prob[NENT];                       // 4 KB
    __shared__ int   s_cnt;

    const int bank  = blockIdx.x;
    const int oBase = blockIdx.y * O_CHUNK;
    const int kOff  = blockIdx.z * KRANGE;
    const int tid   = threadIdx.x;
    const int warp  = tid >> 5;
    const int lane  = tid & 31;
    const int gr    = lane >> 2;   // group id 0..7
    const int tg    = lane & 3;    // thread-in-group 0..3
    const int o0    = oBase + warp * 16;

    if (tid == 0) s_cnt = 0;
    __syncthreads();

    for (int e = tid; e < NENT; e += NTHR) {
        if (sel[e] == bank) {
            int pos = atomicAdd(&s_cnt, 1);
            s_tok[pos]  = e / KSEL;
            s_prob[pos] = prob[e];
        }
    }
    __syncthreads();
    const int count = s_cnt;
    if (count == 0) return;

    // B-fragment gmem base: W[kOff + kb + tg (+4)][o0 + nt*8 + gr]
    const float* Wt = W + (size_t)bank * IN_DIM * OUT_DIM
                        + (size_t)(kOff + tg) * OUT_DIM + o0 + gr;

    for (int tt = 0; tt < count; tt += MTOK) {
        // ── Stage x tile: prescale, split tf32 hi/lo, A-fragment layout ──
        #pragma unroll
        for (int r = 0; r < 4; r++) {
            int j  = tid + r * NTHR;        // 1024 = 64 k4-groups x 16 tokens
            int t  = j & 15;
            int k4 = j >> 4;
            int e  = tt + t;
            float4 v = make_float4(0.f, 0.f, 0.f, 0.f);
            float  p = 0.f;
            if (e < count) {
                p = s_prob[e];
                v = *(const float4*)(x + (size_t)s_tok[e] * IN_DIM + kOff + k4 * 4);
            }
            float a0 = v.x * p, a1 = v.y * p, a2 = v.z * p, a3 = v.w * p;
            uint32_t h0, l0, h1, l1, h2, l2, h3, l3;
            split_tf32(a0, h0, l0);
            split_tf32(a1, h1, l1);
            split_tf32(a2, h2, l2);
            split_tf32(a3, h3, l3);
            // element (k = k4*4+i, t): lane = (t&7)*4 + i, reg = (k4&1)*2 + (t>>3)
            int ks = k4 >> 1;
            int rg = (k4 & 1) * 2 + (t >> 3);
            int base = ks * 128 + (t & 7) * 16 + rg;   // + i*4 per element
            xs_h[base + 0]  = h0; xs_l[base + 0]  = l0;
            xs_h[base + 4]  = h1; xs_l[base + 4]  = l1;
            xs_h[base + 8]  = h2; xs_l[base + 8]  = l2;
            xs_h[base + 12] = h3; xs_l[base + 12] = l3;
        }

        // ── Prefetch W group 0 (overlaps staging completion) ──
        float w[2][GSTEP][4];
        #pragma unroll
        for (int g = 0; g < GSTEP; g++) {
            const float* wp = Wt + (size_t)(g * 8) * OUT_DIM;
            w[0][g][0] = wp[0];
            w[0][g][1] = wp[4 * OUT_DIM];
            w[0][g][2] = wp[8];
            w[0][g][3] = wp[4 * OUT_DIM + 8];
        }
        __syncthreads();

        float c0[4] = {0.f, 0.f, 0.f, 0.f};
        float c1[4] = {0.f, 0.f, 0.f, 0.f};

        // ── Mainloop: 8 groups x 4 ksteps; next group's W issued before compute ──
        #pragma unroll
        for (int grp = 0; grp < NGRP; grp++) {
            const int cur = grp & 1;
            if (grp + 1 < NGRP) {
                #pragma unroll
                for (int g = 0; g < GSTEP; g++) {
                    const float* wp = Wt + (size_t)((grp + 1) * (GSTEP * 8) + g * 8) * OUT_DIM;
                    w[cur ^ 1][g][0] = wp[0];
                    w[cur ^ 1][g][1] = wp[4 * OUT_DIM];
                    w[cur ^ 1][g][2] = wp[8];
                    w[cur ^ 1][g][3] = wp[4 * OUT_DIM + 8];
                }
            }
            #pragma unroll
            for (int g = 0; g < GSTEP; g++) {
                const int ks = grp * GSTEP + g;
                uint32_t ah[4], al[4];
                *(uint4*)ah = *(const uint4*)&xs_h[ks * 128 + lane * 4];
                *(uint4*)al = *(const uint4*)&xs_l[ks * 128 + lane * 4];

                uint32_t bh0[2], bl0[2], bh1[2], bl1[2];
                split_tf32(w[cur][g][0], bh0[0], bl0[0]);
                split_tf32(w[cur][g][1], bh0[1], bl0[1]);
                split_tf32(w[cur][g][2], bh1[0], bl1[0]);
                split_tf32(w[cur][g][3], bh1[1], bl1[1]);

                mma8(c0, ah, bh0);
                mma8(c0, al, bh0);
                mma8(c0, ah, bl0);
                mma8(c1, ah, bh1);
                mma8(c1, al, bh1);
                mma8(c1, ah, bl1);
            }
        }

        // ── Epilogue: C-fragment scatter; bias only from the z==0 K-half ──
        #pragma unroll
        for (int nt = 0; nt < 2; nt++) {
            const float* cc  = nt ? c1 : c0;
            const int   colb = o0 + nt * 8 + tg * 2;
            float2 bb = make_float2(0.f, 0.f);
            if (kOff == 0) bb = *(const float2*)(bias + (size_t)bank * OUT_DIM + colb);

            int e0 = tt + gr;
            if (e0 < count) {
                float p = s_prob[e0];
                float* po = out + (size_t)s_tok[e0] * OUT_DIM + colb;
                atomicAdd(po + 0, cc[0] + p * bb.x);
                atomicAdd(po + 1, cc[1] + p * bb.y);
            }
            int e1 = tt + gr + 8;
            if (e1 < count) {
                float p = s_prob[e1];
                float* po = out + (size_t)s_tok[e1] * OUT_DIM + colb;
                atomicAdd(po + 0, cc[2] + p * bb.x);
                atomicAdd(po + 1, cc[3] + p * bb.y);
            }
        }
        __syncthreads();   // xs reuse barrier for next token tile
    }
}

extern "C" void kernel_launch(void* const* d_in, const int* in_sizes, int n_in,
                              void* d_out, int out_size) {
    const float* x    = (const float*)d_in[0];
    const int*   sel  = (const int*)  d_in[1];
    const float* prob = (const float*)d_in[2];
    const float* W    = (const float*)d_in[3];
    const float* bias = (const float*)d_in[4];
    float* out = (float*)d_out;

    int n4 = out_size / 4;
    zero_out_kernel<<<(n4 + 255) / 256, 256>>>((float4*)out, n4);

    dim3 grid(NB, O_SPLIT, K_SPLIT);
    banked_linear_mma<<<grid, NTHR>>>(x, sel, prob, W, bias, out);
}

// round 11
// speedup vs baseline: 2.5305x; 1.1729x over previous
#include <cuda_runtime.h>
#include <cuda_bf16.h>
#include <cstdint>

// BankedLinear: B=2, T=256, K=2, IN=OUT=512, NB=64
#define NB       64
#define IN_DIM   512
#define OUT_DIM  512
#define KSEL     2
#define NENT     1024
#define O_SPLIT  4
#define O_CHUNK  128                 // outs per CTA
#define NKS      32                  // k16-steps (full K=512)
#define MTOK     32                  // token tile: 2 m-tiles of 16
#define NTHR     256                 // 8 warps; warp owns 16 outs
#define NSTAGE   5
#define WPAD     132                 // padded floats per W row (conflict-free LDS)
#define STAGE_B  (16 * WPAD * 4)     // 8448 bytes per stage

// dynamic smem layout (16B-aligned offsets)
#define OFF_XH   0                         // 32 KB: A-frag bf16x2 hi
#define OFF_XL   32768                     // 32 KB: A-frag bf16x2 lo
#define OFF_WS   65536                     // 5 x 8448 = 42240
#define OFF_ENT  (OFF_WS + NSTAGE * STAGE_B)   // 107776: 1024 u16
#define OFF_CNT  (OFF_ENT + 2048)              // 109824
#define SMEM_BYTES (OFF_CNT + 16)              // 109840

__global__ void zero_out_kernel(float4* __restrict__ out, int n4) {
    int i = blockIdx.x * blockDim.x + threadIdx.x;
    if (i < n4) out[i] = make_float4(0.f, 0.f, 0.f, 0.f);
}

__device__ __forceinline__ void cp_async16(void* dst, const void* src) {
    unsigned d = (unsigned)__cvta_generic_to_shared(dst);
    asm volatile("cp.async.cg.shared.global [%0], [%1], 16;\n" :: "r"(d), "l"(src));
}
#define CP_COMMIT() asm volatile("cp.async.commit_group;\n" ::)
#define CP_WAIT3()  asm volatile("cp.async.wait_group 3;\n" ::)

__device__ __forceinline__ uint32_t pack2(__nv_bfloat16 lo, __nv_bfloat16 hi) {
    uint32_t u;
    asm("mov.b32 %0, {%1, %2};" : "=r"(u)
        : "h"(__bfloat16_as_ushort(lo)), "h"(__bfloat16_as_ushort(hi)));
    return u;
}
__device__ __forceinline__ void splitbf(float f, __nv_bfloat16& h, __nv_bfloat16& l) {
    h = __float2bfloat16_rn(f);
    l = __float2bfloat16_rn(f - __bfloat162float(h));
}
__device__ __forceinline__ void mma16(float* c, const uint32_t* a, const uint32_t* b) {
    asm volatile(
        "mma.sync.aligned.m16n8k16.row.col.f32.bf16.bf16.f32 "
        "{%0,%1,%2,%3}, {%4,%5,%6,%7}, {%8,%9}, {%0,%1,%2,%3};"
        : "+f"(c[0]), "+f"(c[1]), "+f"(c[2]), "+f"(c[3])
        : "r"(a[0]), "r"(a[1]), "r"(a[2]), "r"(a[3]), "r"(b[0]), "r"(b[1]));
}

__global__ __launch_bounds__(NTHR, 2)
void banked_linear_bf16(const float* __restrict__ x,     // [BT, IN]
                        const int*   __restrict__ sel,   // [BT, K]
                        const float* __restrict__ prob,  // [BT, K]
                        const float* __restrict__ W,     // [NB, IN, OUT]
                        const float* __restrict__ bias,  // [NB, OUT]
                        float*       __restrict__ out)   // [BT, OUT]
{
    extern __shared__ __align__(16) char dsm[];
    uint32_t*       xs_h  = (uint32_t*)(dsm + OFF_XH);
    uint32_t*       xs_l  = (uint32_t*)(dsm + OFF_XL);
    float*          ws    = (float*)(dsm + OFF_WS);
    unsigned short* s_ent = (unsigned short*)(dsm + OFF_ENT);
    int*            s_cnt = (int*)(dsm + OFF_CNT);

    const int bank  = blockIdx.x;
    const int oBase = blockIdx.y * O_CHUNK;
    const int tid   = threadIdx.x;
    const int warp  = tid >> 5;
    const int lane  = tid & 31;
    const int gr    = lane >> 2;
    const int tg    = lane & 3;
    const int wcol  = warp * 16;          // warp's col offset within the 128-chunk

    if (tid == 0) *s_cnt = 0;
    __syncthreads();

    for (int e = tid; e < NENT; e += NTHR) {
        if (sel[e] == bank) {
            int pos = atomicAdd(s_cnt, 1);
            s_ent[pos] = (unsigned short)e;
        }
    }
    __syncthreads();
    const int count = *s_cnt;
    if (count == 0) return;

    const float* Wc = W + (size_t)bank * IN_DIM * OUT_DIM + oBase;   // rows k, 128 cols
    float2 bb[2];
    bb[0] = *(const float2*)(bias + (size_t)bank * OUT_DIM + oBase + wcol + tg * 2);
    bb[1] = *(const float2*)(bias + (size_t)bank * OUT_DIM + oBase + wcol + 8 + tg * 2);

    for (int tt = 0; tt < count; tt += MTOK) {
        // ── prologue: launch W stages 0..3 ──
        #pragma unroll
        for (int s = 0; s < NSTAGE - 1; s++) {
            #pragma unroll
            for (int q = 0; q < 2; q++) {
                int idx = tid + q * NTHR;       // 512 chunks: 16 rows x 32 x 16B
                int row = idx >> 5, c16 = idx & 31;
                cp_async16(dsm + OFF_WS + s * STAGE_B + row * (WPAD * 4) + c16 * 16,
                           Wc + (size_t)(s * 16 + row) * OUT_DIM + c16 * 4);
            }
            CP_COMMIT();
        }

        // ── stage x: prob-prescale, bf16 hi/lo split, A-fragment layout ──
        #pragma unroll
        for (int it = 0; it < 16; it++) {
            int j = tid + it * NTHR;      // 4096 = 32 slots x 128 k4-groups
            int t = j & 31;
            int q = j >> 5;               // k4-group 0..127
            int e = tt + t;
            float4 v = make_float4(0.f, 0.f, 0.f, 0.f);
            float  p = 0.f;
            if (e < count) {
                int ge = s_ent[e];
                p = prob[ge];
                v = *(const float4*)(x + (size_t)(ge >> 1) * IN_DIM + q * 4);
            }
            __nv_bfloat16 h0, l0, h1, l1, h2, l2, h3, l3;
            splitbf(v.x * p, h0, l0);
            splitbf(v.y * p, h1, l1);
            splitbf(v.z * p, h2, l2);
            splitbf(v.w * p, h3, l3);
            // fragment indices (m16n8k16 A): elem (trow, kk) -> lane(gr,tg), reg j
            int trow = t & 15, mt = t >> 4;
            int grs = trow & 7, jb = trow >> 3;
            int ks = q >> 2;
            int kk = (q & 3) * 4;
            int tgA = (kk >> 1) & 3,       jA = jb + 2 * (kk >> 3);
            int tgB = ((kk + 2) >> 1) & 3, jB = jb + 2 * ((kk + 2) >> 3);
            int base = ks * 256 + mt * 128;
            int wA = base + (grs * 4 + tgA) * 4 + jA;
            int wB = base + (grs * 4 + tgB) * 4 + jB;
            xs_h[wA] = pack2(h0, h1);  xs_h[wB] = pack2(h2, h3);
            xs_l[wA] = pack2(l0, l1);  xs_l[wB] = pack2(l2, l3);
        }
        __syncthreads();

        float c[2][2][4];
        #pragma unroll
        for (int mt = 0; mt < 2; mt++)
            #pragma unroll
            for (int nt = 0; nt < 2; nt++)
                #pragma unroll
                for (int i = 0; i < 4; i++) c[mt][nt][i] = 0.f;

        // ── mainloop: 32 k16-steps through the cp.async ring ──
        for (int ks = 0; ks < NKS; ks++) {
            CP_WAIT3();          // stage ks complete (groups retire in order)
            __syncthreads();     // visible to all warps; prior slot free

            int nks = ks + NSTAGE - 1;
            if (nks < NKS) {
                int slot = nks % NSTAGE;
                #pragma unroll
                for (int q = 0; q < 2; q++) {
                    int idx = tid + q * NTHR;
                    int row = idx >> 5, c16 = idx & 31;
                    cp_async16(dsm + OFF_WS + slot * STAGE_B + row * (WPAD * 4) + c16 * 16,
                               Wc + (size_t)(nks * 16 + row) * OUT_DIM + c16 * 4);
                }
            }
            CP_COMMIT();         // commit every iter (possibly empty) to keep counts aligned

            const float* wsf = ws + (ks % NSTAGE) * (16 * WPAD);

            // B fragments: rows 2tg,2tg+1,2tg+8,2tg+9; cols wcol + nt*8 + gr
            uint32_t bh[2][2], bl[2][2];
            #pragma unroll
            for (int nt = 0; nt < 2; nt++) {
                int cc = wcol + nt * 8 + gr;
                float w0 = wsf[(2 * tg) * WPAD + cc];
                float w1 = wsf[(2 * tg + 1) * WPAD + cc];
                float w2 = wsf[(2 * tg + 8) * WPAD + cc];
                float w3 = wsf[(2 * tg + 9) * WPAD + cc];
                __nv_bfloat16 h0, l0, h1, l1, h2, l2, h3, l3;
                splitbf(w0, h0, l0);
                splitbf(w1, h1, l1);
                splitbf(w2, h2, l2);
                splitbf(w3, h3, l3);
                bh[nt][0] = pack2(h0, h1);  bh[nt][1] = pack2(h2, h3);
                bl[nt][0] = pack2(l0, l1);  bl[nt][1] = pack2(l2, l3);
            }

            #pragma unroll
            for (int mt = 0; mt < 2; mt++) {
                uint32_t ah[4], al[4];
                *(uint4*)ah = *(const uint4*)&xs_h[ks * 256 + mt * 128 + lane * 4];
                *(uint4*)al = *(const uint4*)&xs_l[ks * 256 + mt * 128 + lane * 4];
                #pragma unroll
                for (int nt = 0; nt < 2; nt++) {
                    mma16(c[mt][nt], ah, bh[nt]);   // hi*hi
                    mma16(c[mt][nt], al, bh[nt]);   // lo*hi
                    mma16(c[mt][nt], ah, bl[nt]);   // hi*lo
                }
            }
        }

        // ── epilogue: vector red (acc prob-prescaled; add p*bias) ──
        #pragma unroll
        for (int mt = 0; mt < 2; mt++) {
            #pragma unroll
            for (int nt = 0; nt < 2; nt++) {
                int colb = oBase + wcol + nt * 8 + tg * 2;
                int s0 = tt + mt * 16 + gr;
                if (s0 < count) {
                    int ge = s_ent[s0];
                    float p = prob[ge];
                    float* po = out + (size_t)(ge >> 1) * OUT_DIM + colb;
                    float v0 = c[mt][nt][0] + p * bb[nt].x;
                    float v1 = c[mt][nt][1] + p * bb[nt].y;
                    asm volatile("red.global.add.v2.f32 [%0], {%1, %2};"
                                 :: "l"(po), "f"(v0), "f"(v1) : "memory");
                }
                int s1 = tt + mt * 16 + gr + 8;
                if (s1 < count) {
                    int ge = s_ent[s1];
                    float p = prob[ge];
                    float* po = out + (size_t)(ge >> 1) * OUT_DIM + colb;
                    float v0 = c[mt][nt][2] + p * bb[nt].x;
                    float v1 = c[mt][nt][3] + p * bb[nt].y;
                    asm volatile("red.global.add.v2.f32 [%0], {%1, %2};"
                                 :: "l"(po), "f"(v0), "f"(v1) : "memory");
                }
            }
        }
        __syncthreads();   // xs / ws ring reuse barrier (rare multi-tile case)
    }
}

extern "C" void kernel_launch(void* const* d_in, const int* in_sizes, int n_in,
                              void* d_out, int out_size) {
    const float* x    = (const float*)d_in[0];
    const int*   sel  = (const int*)  d_in[1];
    const float* prob = (const float*)d_in[2];
    const float* W    = (const float*)d_in[3];
    const float* bias = (const float*)d_in[4];
    float* out = (float*)d_out;

    // >48KB dynamic smem requires opting in (idempotent; not a stream op).
    cudaFuncSetAttribute(banked_linear_bf16,
                         cudaFuncAttributeMaxDynamicSharedMemorySize, SMEM_BYTES);

    int n4 = out_size / 4;
    zero_out_kernel<<<(n4 + 255) / 256, 256>>>((float4*)out, n4);

    dim3 grid(NB, O_SPLIT);
    banked_linear_bf16<<<grid, NTHR, SMEM_BYTES>>>(x, sel, prob, W, bias, out);
}

// round 12
// speedup vs baseline: 2.8552x; 1.1283x over previous
#include <cuda_runtime.h>
#include <cuda_bf16.h>
#include <cstdint>

// BankedLinear: B=2, T=256, K=2, IN=OUT=512, NB=64
#define NB       64
#define IN_DIM   512
#define OUT_DIM  512
#define KSEL     2
#define NENT     1024
#define O_SPLIT  4
#define O_CHUNK  128                 // outs per CTA (16 per warp)
#define NKS      32                  // k16-steps (full K=512)
#define MTOK     32                  // token tile: 2 m-tiles of 16
#define NTHR     256                 // 8 warps
#define NSTAGE   4                   // per-warp W ring depth
#define WPITCH   20                  // floats per W row (bank-conflict-free)
#define WSTG_B   (16 * WPITCH * 4)   // 1280 B per stage per warp
#define WRING_B  (NSTAGE * WSTG_B)   // 5120 B per warp

// dynamic smem layout
#define OFF_XH   0                          // 32 KB: A-frag bf16x2 hi
#define OFF_XL   32768                      // 32 KB: A-frag bf16x2 lo
#define OFF_WS   65536                      // 8 warps x 5120 = 40960
#define OFF_ENT  (OFF_WS + 8 * WRING_B)     // 106496: 1024 u16
#define OFF_CNT  (OFF_ENT + 2048)           // 108544
#define SMEM_BYTES (OFF_CNT + 16)           // 108560

__global__ void zero_out_kernel(float4* __restrict__ out, int n4) {
    int i = blockIdx.x * blockDim.x + threadIdx.x;
    if (i < n4) out[i] = make_float4(0.f, 0.f, 0.f, 0.f);
}

__device__ __forceinline__ void cp_async16(void* dst, const void* src) {
    unsigned d = (unsigned)__cvta_generic_to_shared(dst);
    asm volatile("cp.async.cg.shared.global [%0], [%1], 16;\n" :: "r"(d), "l"(src));
}
#define CP_COMMIT() asm volatile("cp.async.commit_group;\n" ::)
#define CP_WAIT3()  asm volatile("cp.async.wait_group 3;\n" ::)
#define CP_WAIT0()  asm volatile("cp.async.wait_group 0;\n" ::)

__device__ __forceinline__ uint32_t pack2(__nv_bfloat16 lo, __nv_bfloat16 hi) {
    uint32_t u;
    asm("mov.b32 %0, {%1, %2};" : "=r"(u)
        : "h"(__bfloat16_as_ushort(lo)), "h"(__bfloat16_as_ushort(hi)));
    return u;
}
__device__ __forceinline__ void splitbf(float f, __nv_bfloat16& h, __nv_bfloat16& l) {
    h = __float2bfloat16_rn(f);
    l = __float2bfloat16_rn(f - __bfloat162float(h));
}
__device__ __forceinline__ void mma16(float* c, const uint32_t* a, const uint32_t* b) {
    asm volatile(
        "mma.sync.aligned.m16n8k16.row.col.f32.bf16.bf16.f32 "
        "{%0,%1,%2,%3}, {%4,%5,%6,%7}, {%8,%9}, {%0,%1,%2,%3};"
        : "+f"(c[0]), "+f"(c[1]), "+f"(c[2]), "+f"(c[3])
        : "r"(a[0]), "r"(a[1]), "r"(a[2]), "r"(a[3]), "r"(b[0]), "r"(b[1]));
}

__global__ __launch_bounds__(NTHR, 2)
void banked_linear_bf16(const float* __restrict__ x,     // [BT, IN]
                        const int*   __restrict__ sel,   // [BT, K]
                        const float* __restrict__ prob,  // [BT, K]
                        const float* __restrict__ W,     // [NB, IN, OUT]
                        const float* __restrict__ bias,  // [NB, OUT]
                        float*       __restrict__ out)   // [BT, OUT]
{
    extern __shared__ __align__(16) char dsm[];
    uint32_t*       xs_h  = (uint32_t*)(dsm + OFF_XH);
    uint32_t*       xs_l  = (uint32_t*)(dsm + OFF_XL);
    unsigned short* s_ent = (unsigned short*)(dsm + OFF_ENT);
    int*            s_cnt = (int*)(dsm + OFF_CNT);

    const int bank  = blockIdx.x;
    const int oBase = blockIdx.y * O_CHUNK;
    const int tid   = threadIdx.x;
    const int warp  = tid >> 5;
    const int lane  = tid & 31;
    const int gr    = lane >> 2;
    const int tg    = lane & 3;
    const int wcol  = warp * 16;

    char* wring = dsm + OFF_WS + warp * WRING_B;   // this warp's private W ring
    float* wringf = (float*)wring;

    if (tid == 0) *s_cnt = 0;
    __syncthreads();

    for (int e = tid; e < NENT; e += NTHR) {
        if (sel[e] == bank) {
            int pos = atomicAdd(s_cnt, 1);
            s_ent[pos] = (unsigned short)e;
        }
    }
    __syncthreads();
    const int count = *s_cnt;
    if (count == 0) return;

    // Warp's 16-col W slice base (rows = k).
    const float* Ww = W + (size_t)bank * IN_DIM * OUT_DIM + oBase + wcol;
    float2 bb[2];
    bb[0] = *(const float2*)(bias + (size_t)bank * OUT_DIM + oBase + wcol + tg * 2);
    bb[1] = *(const float2*)(bias + (size_t)bank * OUT_DIM + oBase + wcol + 8 + tg * 2);

    // Per-warp stage load: 16 rows x 64B = 64 chunks of 16B -> 2 per lane.
    // lane covers (row = lane>>1 ... ) : chunk idx = lane*2+q -> row = idx>>2, c16 = idx&3
    for (int tt = 0; tt < count; tt += MTOK) {
        // ── prologue: stages 0..2 into the warp-private ring ──
        #pragma unroll
        for (int s = 0; s < NSTAGE - 1; s++) {
            #pragma unroll
            for (int q = 0; q < 2; q++) {
                int idx = lane * 2 + q;
                int row = idx >> 2, c16 = idx & 3;
                cp_async16(wring + s * WSTG_B + row * (WPITCH * 4) + c16 * 16,
                           Ww + (size_t)(s * 16 + row) * OUT_DIM + c16 * 4);
            }
            CP_COMMIT();
        }

        // ── stage x cooperatively: prescale, bf16 hi/lo split, A-frag layout ──
        #pragma unroll
        for (int it = 0; it < 16; it++) {
            int j = tid + it * NTHR;      // 4096 = 32 slots x 128 k4-groups
            int t = j & 31;
            int q = j >> 5;
            int e = tt + t;
            float4 v = make_float4(0.f, 0.f, 0.f, 0.f);
            float  p = 0.f;
            if (e < count) {
                int ge = s_ent[e];
                p = prob[ge];
                v = *(const float4*)(x + (size_t)(ge >> 1) * IN_DIM + q * 4);
            }
            __nv_bfloat16 h0, l0, h1, l1, h2, l2, h3, l3;
            splitbf(v.x * p, h0, l0);
            splitbf(v.y * p, h1, l1);
            splitbf(v.z * p, h2, l2);
            splitbf(v.w * p, h3, l3);
            int trow = t & 15, mt = t >> 4;
            int grs = trow & 7, jb = trow >> 3;
            int ks = q >> 2;
            int kk = (q & 3) * 4;
            int tgA = (kk >> 1) & 3,       jA = jb + 2 * (kk >> 3);
            int tgB = ((kk + 2) >> 1) & 3, jB = jb + 2 * ((kk + 2) >> 3);
            int base = ks * 256 + mt * 128;
            int wA = base + (grs * 4 + tgA) * 4 + jA;
            int wB = base + (grs * 4 + tgB) * 4 + jB;
            xs_h[wA] = pack2(h0, h1);  xs_h[wB] = pack2(h2, h3);
            xs_l[wA] = pack2(l0, l1);  xs_l[wB] = pack2(l2, l3);
        }
        __syncthreads();   // xs visible to all warps; warps free-run from here

        float c[2][2][4];
        #pragma unroll
        for (int mt = 0; mt < 2; mt++)
            #pragma unroll
            for (int nt = 0; nt < 2; nt++)
                #pragma unroll
                for (int i = 0; i < 4; i++) c[mt][nt][i] = 0.f;

        // ── mainloop: NO barriers — per-warp ring, per-warp waits ──
        for (int ks = 0; ks < NKS; ks++) {
            // issue stage ks+3 (commit even when empty to keep group counts aligned)
            int nks = ks + NSTAGE - 1;
            if (nks < NKS) {
                int slot = nks & (NSTAGE - 1);
                #pragma unroll
                for (int q = 0; q < 2; q++) {
                    int idx = lane * 2 + q;
                    int row = idx >> 2, c16 = idx & 3;
                    cp_async16(wring + slot * WSTG_B + row * (WPITCH * 4) + c16 * 16,
                               Ww + (size_t)(nks * 16 + row) * OUT_DIM + c16 * 4);
                }
            }
            CP_COMMIT();
            CP_WAIT3();          // stage ks complete (warp-local)

            const float* wsf = wringf + (ks & (NSTAGE - 1)) * (16 * WPITCH);

            // B fragments: rows 2tg,2tg+1,2tg+8,2tg+9; cols nt*8+gr (warp-local)
            uint32_t bh[2][2], bl[2][2];
            #pragma unroll
            for (int nt = 0; nt < 2; nt++) {
                int cc = nt * 8 + gr;
                float w0 = wsf[(2 * tg) * WPITCH + cc];
                float w1 = wsf[(2 * tg + 1) * WPITCH + cc];
                float w2 = wsf[(2 * tg + 8) * WPITCH + cc];
                float w3 = wsf[(2 * tg + 9) * WPITCH + cc];
                __nv_bfloat16 h0, l0, h1, l1, h2, l2, h3, l3;
                splitbf(w0, h0, l0);
                splitbf(w1, h1, l1);
                splitbf(w2, h2, l2);
                splitbf(w3, h3, l3);
                bh[nt][0] = pack2(h0, h1);  bh[nt][1] = pack2(h2, h3);
                bl[nt][0] = pack2(l0, l1);  bl[nt][1] = pack2(l2, l3);
            }

            #pragma unroll
            for (int mt = 0; mt < 2; mt++) {
                uint32_t ah[4], al[4];
                *(uint4*)ah = *(const uint4*)&xs_h[ks * 256 + mt * 128 + lane * 4];
                *(uint4*)al = *(const uint4*)&xs_l[ks * 256 + mt * 128 + lane * 4];
                #pragma unroll
                for (int nt = 0; nt < 2; nt++) {
                    mma16(c[mt][nt], ah, bh[nt]);   // hi*hi
                    mma16(c[mt][nt], al, bh[nt]);   // lo*hi
                    mma16(c[mt][nt], ah, bl[nt]);   // hi*lo
                }
            }
        }
        CP_WAIT0();   // retire any stragglers before ring/xs reuse

        // ── epilogue: vector red (acc prob-prescaled; add p*bias) ──
        #pragma unroll
        for (int mt = 0; mt < 2; mt++) {
            #pragma unroll
            for (int nt = 0; nt < 2; nt++) {
                int colb = oBase + wcol + nt * 8 + tg * 2;
                int s0 = tt + mt * 16 + gr;
                if (s0 < count) {
                    int ge = s_ent[s0];
                    float p = prob[ge];
                    float* po = out + (size_t)(ge >> 1) * OUT_DIM + colb;
                    float v0 = c[mt][nt][0] + p * bb[nt].x;
                    float v1 = c[mt][nt][1] + p * bb[nt].y;
                    asm volatile("red.global.add.v2.f32 [%0], {%1, %2};"
                                 :: "l"(po), "f"(v0), "f"(v1) : "memory");
                }
                int s1 = tt + mt * 16 + gr + 8;
                if (s1 < count) {
                    int ge = s_ent[s1];
                    float p = prob[ge];
                    float* po = out + (size_t)(ge >> 1) * OUT_DIM + colb;
                    float v0 = c[mt][nt][2] + p * bb[nt].x;
                    float v1 = c[mt][nt][3] + p * bb[nt].y;
                    asm volatile("red.global.add.v2.f32 [%0], {%1, %2};"
                                 :: "l"(po), "f"(v0), "f"(v1) : "memory");
                }
            }
        }
        __syncthreads();   // xs reuse barrier (rare multi-tile case)
    }
}

extern "C" void kernel_launch(void* const* d_in, const int* in_sizes, int n_in,
                              void* d_out, int out_size) {
    const float* x    = (const float*)d_in[0];
    const int*   sel  = (const int*)  d_in[1];
    const float* prob = (const float*)d_in[2];
    const float* W    = (const float*)d_in[3];
    const float* bias = (const float*)d_in[4];
    float* out = (float*)d_out;

    cudaFuncSetAttribute(banked_linear_bf16,
                         cudaFuncAttributeMaxDynamicSharedMemorySize, SMEM_BYTES);

    int n4 = out_size / 4;
    zero_out_kernel<<<(n4 + 255) / 256, 256>>>((float4*)out, n4);

    dim3 grid(NB, O_SPLIT);
    banked_linear_bf16<<<grid, NTHR, SMEM_BYTES>>>(x, sel, prob, W, bias, out);
}